// round 11
// baseline (speedup 1.0000x reference)
#include <cuda_runtime.h>
#include <math.h>

#define Bq   8
#define Nn   20000
#define Ee   320000
#define BN   (Bq*Nn)        // 160000
#define BE   (Bq*Ee)        // 2560000
#define TWOE (2*Ee)         // 640000
#define HID  128
#define EMB  64
#define CAP  64             // max degree bucket (Poisson(16): P(>=64) ~ 2e-18)
#define HSTR 132            // Hs row stride (floats)
#define ASTR 68             // mlp2 As row stride (floats)

typedef unsigned long long ull;

// ---- packed fp32x2 helpers (Blackwell FFMA2: 2 FMAs per issue slot) ----
__device__ __forceinline__ ull pack2(float lo, float hi) {
    ull r;
    asm("mov.b64 %0, {%1, %2};" : "=l"(r) : "f"(lo), "f"(hi));
    return r;
}
__device__ __forceinline__ void unpack2(ull v, float &lo, float &hi) {
    asm("mov.b64 {%0, %1}, %2;" : "=f"(lo), "=f"(hi) : "l"(v));
}
__device__ __forceinline__ void fma2(ull &d, ull a, ull b) {
    asm("fma.rn.f32x2 %0, %1, %2, %0;" : "+l"(d) : "l"(a), "l"(b));
}
__device__ __forceinline__ float f4c(const float4 &v, int s) {
    return s == 0 ? v.x : (s == 1 ? v.y : (s == 2 ? v.z : v.w));
}

// ---------------- scratch (device globals; no runtime allocation) ----------------
__device__ __align__(16) int   g_cnt[BN];
__device__ __align__(16) int   g_adj[BN*CAP];
__device__ __align__(16) float g_x0[BN*4];
__device__ __align__(16) float g_h1[BN*4];
__device__ __align__(16) float g_x1[BN*EMB];
__device__ __align__(16) float g_h2[BN*EMB];
__device__ __align__(16) float g_pooled[Bq*EMB];
__device__ __align__(16) float g_hidden[Bq*HID];

// ---------------- zero counters + pooled + build x0 ----------------
__global__ void init_kernel(const float* __restrict__ actions, const float* __restrict__ nf) {
    int i = blockIdx.x * blockDim.x + threadIdx.x;
    if (i < BN) {
        g_cnt[i] = 0;
        float4 v;
        v.x = actions[2*i];
        v.y = actions[2*i + 1];
        v.z = nf[i];
        v.w = 0.f;
        reinterpret_cast<float4*>(g_x0)[i] = v;
    }
    if (i < Bq*EMB) g_pooled[i] = 0.f;
}

// ---------------- build adjacency buckets -----------------------------------
__global__ void fill_adj(const int* __restrict__ ei) {
    int j = blockIdx.x * blockDim.x + threadIdx.x;
    if (j < BE) {
        int s = ei[j]      + (j / TWOE) * Nn;
        int d = ei[j + BE] + ((j + BE) / TWOE) * Nn;
        int pos = atomicAdd(&g_cnt[d], 1);
        if (pos < CAP) g_adj[d*CAP + pos] = s;
    }
}

// ---------------- conv1 gather: h1[n] = x0[n] + sum x0[adj(n)] ----------------
__global__ void gather1() {
    int tid = blockIdx.x * blockDim.x + threadIdx.x;
    int n = tid >> 2, t = tid & 3;
    if (n >= BN) return;
    int deg = min(g_cnt[n], CAP);
    float4 a = make_float4(0.f, 0.f, 0.f, 0.f);
    const float4* x0 = reinterpret_cast<const float4*>(g_x0);
    for (int i = t; i < deg; i += 4) {
        float4 v = x0[g_adj[n*CAP + i]];
        a.x += v.x; a.y += v.y; a.z += v.z; a.w += v.w;
    }
#pragma unroll
    for (int off = 2; off >= 1; off >>= 1) {
        a.x += __shfl_xor_sync(0xffffffffu, a.x, off);
        a.y += __shfl_xor_sync(0xffffffffu, a.y, off);
        a.z += __shfl_xor_sync(0xffffffffu, a.z, off);
        a.w += __shfl_xor_sync(0xffffffffu, a.w, off);
    }
    if (t == 0) {
        float4 s = x0[n];
        s.x += a.x; s.y += a.y; s.z += a.z; s.w += a.w;
        reinterpret_cast<float4*>(g_h1)[n] = s;
    }
}

// ---------------- conv2 gather: h2[n] = x1[n] + sum x1[adj(n)] ----------------
__global__ void gather2() {
    int tid = blockIdx.x * blockDim.x + threadIdx.x;
    int n = tid >> 4, t = tid & 15;
    if (n >= BN) return;
    int deg = min(g_cnt[n], CAP);
    const float4* x1 = reinterpret_cast<const float4*>(g_x1);
    float4 a = x1[n*16 + t];                      // self term
    const int* row = &g_adj[n*CAP];
#pragma unroll 4
    for (int i = 0; i < deg; i++) {
        float4 v = x1[row[i]*16 + t];
        a.x += v.x; a.y += v.y; a.z += v.z; a.w += v.w;
    }
    reinterpret_cast<float4*>(g_h2)[n*16 + t] = a;
}

// =====================================================================
// MLP 1 : x1 = relu( relu(h1@W1+b1) @ W2 + b2 ), K=3.
// 128 nodes/block, 512 threads (16tx x 32ty): 4-row thread tiles.
// =====================================================================
__global__ void __launch_bounds__(512, 2) mlp1_kernel(const float* __restrict__ W1,
                                                      const float* __restrict__ b1,
                                                      const float* __restrict__ W2,
                                                      const float* __restrict__ b2)
{
    extern __shared__ float sm[];
    float* As  = sm;                  // 512
    float* W1s = sm + 512;            // 512 (384 used)
    float* W2s = sm + 1024;           // 8192
    float* Hs  = sm + 9216;           // 128*HSTR = 16896
    float* b1s = sm + 9216 + 128*HSTR;            // 128
    float* b2s = b1s + 128;                       // 64

    int tid = threadIdx.x;
    int tx = tid & 15, ty = tid >> 4;             // 16 x 32
    int node0 = blockIdx.x * 128;

    for (int e = tid; e < 512; e += 512) As[e] = g_h1[node0*4 + e];
    for (int e = tid; e < 3*HID; e += 512) W1s[e] = W1[e];
    for (int e = tid; e < HID*EMB; e += 512) W2s[e] = W2[e];
    if (tid < HID) b1s[tid] = b1[tid];
    if (tid < EMB) b2s[tid] = b2[tid];
    __syncthreads();

    // ---- layer 1 (K=3): rows ty*4+i, cols tx*8 ----
    ull acc[4][4];
#pragma unroll
    for (int i = 0; i < 4; i++)
#pragma unroll
        for (int j = 0; j < 4; j++)
            acc[i][j] = pack2(b1s[tx*8 + 2*j], b1s[tx*8 + 2*j + 1]);
#pragma unroll
    for (int k = 0; k < 3; k++) {
        float4 w0 = *reinterpret_cast<const float4*>(&W1s[k*HID + tx*8]);
        float4 w1 = *reinterpret_cast<const float4*>(&W1s[k*HID + tx*8 + 4]);
        ull wp[4] = {pack2(w0.x, w0.y), pack2(w0.z, w0.w),
                     pack2(w1.x, w1.y), pack2(w1.z, w1.w)};
#pragma unroll
        for (int i = 0; i < 4; i++) {
            float av = As[(ty*4 + i)*4 + k];
            ull ap = pack2(av, av);
#pragma unroll
            for (int j = 0; j < 4; j++) fma2(acc[i][j], ap, wp[j]);
        }
    }
    // relu -> Hs[128][HSTR]
#pragma unroll
    for (int i = 0; i < 4; i++) {
        float v[8];
#pragma unroll
        for (int j = 0; j < 4; j++) unpack2(acc[i][j], v[2*j], v[2*j+1]);
        float4 r0, r1;
        r0.x = fmaxf(v[0], 0.f); r0.y = fmaxf(v[1], 0.f);
        r0.z = fmaxf(v[2], 0.f); r0.w = fmaxf(v[3], 0.f);
        r1.x = fmaxf(v[4], 0.f); r1.y = fmaxf(v[5], 0.f);
        r1.z = fmaxf(v[6], 0.f); r1.w = fmaxf(v[7], 0.f);
        *reinterpret_cast<float4*>(&Hs[(ty*4 + i)*HSTR + tx*8])     = r0;
        *reinterpret_cast<float4*>(&Hs[(ty*4 + i)*HSTR + tx*8 + 4]) = r1;
    }
    __syncthreads();

    // ---- layer 2: rows ty*4+i (128), cols tx*4 (64) ----
    ull acc2[4][2];
#pragma unroll
    for (int i = 0; i < 4; i++)
#pragma unroll
        for (int j = 0; j < 2; j++)
            acc2[i][j] = pack2(b2s[tx*4 + 2*j], b2s[tx*4 + 2*j + 1]);

    for (int k4 = 0; k4 < 32; k4++) {
        float4 a[4];
#pragma unroll
        for (int i = 0; i < 4; i++)
            a[i] = *reinterpret_cast<const float4*>(&Hs[(ty*4 + i)*HSTR + k4*4]);
#pragma unroll
        for (int s = 0; s < 4; s++) {
            int k = k4*4 + s;
            float4 w = *reinterpret_cast<const float4*>(&W2s[k*EMB + tx*4]);
            ull wp0 = pack2(w.x, w.y), wp1 = pack2(w.z, w.w);
#pragma unroll
            for (int i = 0; i < 4; i++) {
                float av = f4c(a[i], s);
                ull ap = pack2(av, av);
                fma2(acc2[i][0], ap, wp0);
                fma2(acc2[i][1], ap, wp1);
            }
        }
    }
#pragma unroll
    for (int i = 0; i < 4; i++) {
        float v0, v1, v2, v3;
        unpack2(acc2[i][0], v0, v1);
        unpack2(acc2[i][1], v2, v3);
        float4 r;
        r.x = fmaxf(v0, 0.f); r.y = fmaxf(v1, 0.f);
        r.z = fmaxf(v2, 0.f); r.w = fmaxf(v3, 0.f);
        reinterpret_cast<float4*>(g_x1)[(node0 + ty*4 + i)*16 + tx] = r;
    }
}

// =====================================================================
// MLP 2 + pool. 128 nodes/block, 512 threads. Phase-union smem:
// [0,16896): phase1 = As(128*ASTR=8704)+W1(8192); phase2 = Hs(128*HSTR).
// =====================================================================
__global__ void __launch_bounds__(512, 2) mlp2_kernel(const float* __restrict__ W1,
                                                      const float* __restrict__ b1,
                                                      const float* __restrict__ W2,
                                                      const float* __restrict__ b2)
{
    extern __shared__ float sm[];
    float* As  = sm;                  // phase1: 128*ASTR = 8704
    float* W1s = sm + 8704;           // phase1: 8192
    float* Hs  = sm;                  // phase2: 128*HSTR = 16896 (overlay)
    float* W2s = sm + 16896;          // 8192
    float* b1s = sm + 25088;          // 128
    float* b2s = b1s + 128;           // 64
    float* ps  = b2s + 64;            // 128 pool slots (2 batches)

    int tid = threadIdx.x;
    int tx = tid & 15, ty = tid >> 4;             // 16 x 32
    int node0 = blockIdx.x * 128;
    int b0 = node0 / Nn;

    for (int e = tid; e < 128*64; e += 512) {
        int m = e >> 6, c = e & 63;
        As[m*ASTR + c] = g_h2[node0*64 + e];
    }
    for (int e = tid; e < EMB*HID; e += 512) W1s[e] = W1[e];
    for (int e = tid; e < HID*EMB; e += 512) W2s[e] = W2[e];
    if (tid < HID) b1s[tid] = b1[tid];
    if (tid < EMB) b2s[tid] = b2[tid];
    if (tid < 128) ps[tid] = 0.f;
    __syncthreads();

    // ---- layer 1: rows ty*4+i, cols tx*8; K=64 ----
    ull acc[4][4];
#pragma unroll
    for (int i = 0; i < 4; i++)
#pragma unroll
        for (int j = 0; j < 4; j++)
            acc[i][j] = pack2(b1s[tx*8 + 2*j], b1s[tx*8 + 2*j + 1]);

    for (int k4 = 0; k4 < 16; k4++) {
        float4 a[4];
#pragma unroll
        for (int i = 0; i < 4; i++)
            a[i] = *reinterpret_cast<const float4*>(&As[(ty*4 + i)*ASTR + k4*4]);
#pragma unroll
        for (int s = 0; s < 4; s++) {
            int k = k4*4 + s;
            float4 w0 = *reinterpret_cast<const float4*>(&W1s[k*HID + tx*8]);
            float4 w1 = *reinterpret_cast<const float4*>(&W1s[k*HID + tx*8 + 4]);
            ull wp[4] = {pack2(w0.x, w0.y), pack2(w0.z, w0.w),
                         pack2(w1.x, w1.y), pack2(w1.z, w1.w)};
#pragma unroll
            for (int i = 0; i < 4; i++) {
                float av = f4c(a[i], s);
                ull ap = pack2(av, av);
#pragma unroll
                for (int j = 0; j < 4; j++) fma2(acc[i][j], ap, wp[j]);
            }
        }
    }
    __syncthreads();                  // all reads of As + W1 complete

    // relu -> Hs (overlays As/W1 region)
#pragma unroll
    for (int i = 0; i < 4; i++) {
        float v[8];
#pragma unroll
        for (int j = 0; j < 4; j++) unpack2(acc[i][j], v[2*j], v[2*j+1]);
        float4 r0, r1;
        r0.x = fmaxf(v[0], 0.f); r0.y = fmaxf(v[1], 0.f);
        r0.z = fmaxf(v[2], 0.f); r0.w = fmaxf(v[3], 0.f);
        r1.x = fmaxf(v[4], 0.f); r1.y = fmaxf(v[5], 0.f);
        r1.z = fmaxf(v[6], 0.f); r1.w = fmaxf(v[7], 0.f);
        *reinterpret_cast<float4*>(&Hs[(ty*4 + i)*HSTR + tx*8])     = r0;
        *reinterpret_cast<float4*>(&Hs[(ty*4 + i)*HSTR + tx*8 + 4]) = r1;
    }
    __syncthreads();

    // ---- layer 2: rows ty*4+i (128), cols tx*4 (64) ----
    ull acc2[4][2];
#pragma unroll
    for (int i = 0; i < 4; i++)
#pragma unroll
        for (int j = 0; j < 2; j++)
            acc2[i][j] = pack2(b2s[tx*4 + 2*j], b2s[tx*4 + 2*j + 1]);

    for (int k4 = 0; k4 < 32; k4++) {
        float4 a[4];
#pragma unroll
        for (int i = 0; i < 4; i++)
            a[i] = *reinterpret_cast<const float4*>(&Hs[(ty*4 + i)*HSTR + k4*4]);
#pragma unroll
        for (int s = 0; s < 4; s++) {
            int k = k4*4 + s;
            float4 w = *reinterpret_cast<const float4*>(&W2s[k*EMB + tx*4]);
            ull wp0 = pack2(w.x, w.y), wp1 = pack2(w.z, w.w);
#pragma unroll
            for (int i = 0; i < 4; i++) {
                float av = f4c(a[i], s);
                ull ap = pack2(av, av);
                fma2(acc2[i][0], ap, wp0);
                fma2(acc2[i][1], ap, wp1);
            }
        }
    }

    // relu + pool (register pre-reduce over this thread's 4 rows)
    float osum[2][4] = {{0.f,0.f,0.f,0.f},{0.f,0.f,0.f,0.f}};
#pragma unroll
    for (int i = 0; i < 4; i++) {
        float v[4];
        unpack2(acc2[i][0], v[0], v[1]);
        unpack2(acc2[i][1], v[2], v[3]);
        int node = node0 + ty*4 + i;
        int slot = (node / Nn == b0) ? 0 : 1;
#pragma unroll
        for (int j = 0; j < 4; j++) {
            float r = fmaxf(v[j], 0.f);
            if (slot == 0) osum[0][j] += r; else osum[1][j] += r;
        }
    }
#pragma unroll
    for (int s = 0; s < 2; s++)
#pragma unroll
        for (int j = 0; j < 4; j++)
            if (osum[s][j] != 0.f) atomicAdd(&ps[s*64 + tx*4 + j], osum[s][j]);
    __syncthreads();

    if (tid < 128) {
        int slot = tid >> 6, c = tid & 63;
        int b = b0 + slot;
        if (b < Bq && ps[tid] != 0.f) atomicAdd(&g_pooled[b*EMB + c], ps[tid]);
    }
}

// ---------------- hidden = relu(pooled @ mlp_w + mlp_b)  [8 x 128] ----------------
__global__ void head_kernel(const float* __restrict__ mlp_w, const float* __restrict__ mlp_b) {
    int t = threadIdx.x;              // 1024
    int b = t >> 7, l = t & 127;
    float acc = mlp_b[l];
    for (int k = 0; k < EMB; k++)
        acc += g_pooled[b*EMB + k] * mlp_w[k*HID + l];
    g_hidden[t] = fmaxf(acc, 0.f);
}

// ---------------- out = sigmoid(hidden @ out_w + out_b)  [8 x N] ----------------
__global__ void __launch_bounds__(512) out_kernel(const float* __restrict__ out_w,
                                                  const float* __restrict__ out_b,
                                                  float* __restrict__ out) {
    __shared__ float hs[Bq*HID];
    __shared__ float red[Bq*512];
    int tid = threadIdx.x;
    for (int e = tid; e < Bq*HID; e += 512) hs[e] = g_hidden[e];
    __syncthreads();
    int nl = tid & 127, hg = tid >> 7;
    int n = blockIdx.x * 128 + nl;
    float acc[Bq];
#pragma unroll
    for (int b = 0; b < Bq; b++) acc[b] = 0.f;
    if (n < Nn) {
        int h0 = hg * 32;
        for (int h = h0; h < h0 + 32; h++) {
            float w = out_w[h*Nn + n];
#pragma unroll
            for (int b = 0; b < Bq; b++) acc[b] += hs[b*HID + h] * w;
        }
    }
#pragma unroll
    for (int b = 0; b < Bq; b++) red[b*512 + hg*128 + nl] = acc[b];
    __syncthreads();
    if (hg == 0 && n < Nn) {
        float ob = out_b[n];
#pragma unroll
        for (int b = 0; b < Bq; b++) {
            float s = red[b*512 + nl] + red[b*512 + 128 + nl]
                    + red[b*512 + 256 + nl] + red[b*512 + 384 + nl] + ob;
            out[b*Nn + n] = 1.f / (1.f + expf(-s));
        }
    }
}

// ---------------- launch ----------------
extern "C" void kernel_launch(void* const* d_in, const int* in_sizes, int n_in,
                              void* d_out, int out_size) {
    const float* actions = (const float*)d_in[0];
    const float* nf      = (const float*)d_in[1];
    const int*   ei      = (const int*)d_in[2];     // int32 (JAX x64 disabled)
    const float* c1w1 = (const float*)d_in[3];
    const float* c1b1 = (const float*)d_in[4];
    const float* c1w2 = (const float*)d_in[5];
    const float* c1b2 = (const float*)d_in[6];
    const float* c2w1 = (const float*)d_in[7];
    const float* c2b1 = (const float*)d_in[8];
    const float* c2w2 = (const float*)d_in[9];
    const float* c2b2 = (const float*)d_in[10];
    const float* mlpw = (const float*)d_in[11];
    const float* mlpb = (const float*)d_in[12];
    const float* outw = (const float*)d_in[13];
    const float* outb = (const float*)d_in[14];
    float* out = (float*)d_out;

    const int SMEM1 = (9216 + 128*HSTR + 128 + 64) * 4;          // 104,192 B
    const int SMEM2 = (16896 + 8192 + 128 + 64 + 128) * 4;       // 101,632 B
    cudaFuncSetAttribute(mlp1_kernel, cudaFuncAttributeMaxDynamicSharedMemorySize, SMEM1);
    cudaFuncSetAttribute(mlp2_kernel, cudaFuncAttributeMaxDynamicSharedMemorySize, SMEM2);

    init_kernel<<<(BN + 255)/256, 256>>>(actions, nf);
    fill_adj<<<(BE + 255)/256, 256>>>(ei);
    gather1<<<(BN*4 + 255)/256, 256>>>();
    mlp1_kernel<<<BN/128, 512, SMEM1>>>(c1w1, c1b1, c1w2, c1b2);
    gather2<<<(BN*16 + 255)/256, 256>>>();
    mlp2_kernel<<<BN/128, 512, SMEM2>>>(c2w1, c2b1, c2w2, c2b2);
    head_kernel<<<1, 1024>>>(mlpw, mlpb);
    out_kernel<<<(Nn + 127)/128, 512>>>(outw, outb, out);
}

// round 14
// speedup vs baseline: 2.1069x; 2.1069x over previous
#include <cuda_runtime.h>
#include <cuda_fp16.h>
#include <math.h>

#define Bq   8
#define Nn   20000
#define Ee   320000
#define BN   (Bq*Nn)        // 160000
#define BE   (Bq*Ee)        // 2560000
#define TWOE (2*Ee)         // 640000
#define HID  128
#define EMB  64
#define CAP  64             // max degree bucket (Poisson(16): P(>=64) ~ 2e-18)
#define HSTR 132            // Hs row stride (floats)

typedef unsigned long long ull;

// ---- packed fp32x2 helpers (Blackwell FFMA2: 2 FMAs per issue slot) ----
__device__ __forceinline__ ull pack2(float lo, float hi) {
    ull r;
    asm("mov.b64 %0, {%1, %2};" : "=l"(r) : "f"(lo), "f"(hi));
    return r;
}
__device__ __forceinline__ void unpack2(ull v, float &lo, float &hi) {
    asm("mov.b64 {%0, %1}, %2;" : "=f"(lo), "=f"(hi) : "l"(v));
}
__device__ __forceinline__ void fma2(ull &d, ull a, ull b) {
    asm("fma.rn.f32x2 %0, %1, %2, %0;" : "+l"(d) : "l"(a), "l"(b));
}
__device__ __forceinline__ float f4c(const float4 &v, int s) {
    return s == 0 ? v.x : (s == 1 ? v.y : (s == 2 ? v.z : v.w));
}

// ---------------- scratch (device globals; no runtime allocation) ----------------
__device__ __align__(16) int    g_cnt[BN];
__device__ __align__(16) int    g_adj[BN*CAP];
__device__ __align__(16) float  g_x0[BN*4];
__device__ __align__(16) float  g_h1[BN*4];
__device__ __align__(16) __half g_x1h[BN*EMB];   // x1 in fp16 (only gather2 reads it)
__device__ __align__(16) float  g_h2[BN*EMB];
__device__ __align__(16) float  g_pooled[Bq*EMB];
__device__ __align__(16) float  g_hidden[Bq*HID];

// ---------------- zero counters + pooled + build x0 ----------------
__global__ void init_kernel(const float* __restrict__ actions, const float* __restrict__ nf) {
    int i = blockIdx.x * blockDim.x + threadIdx.x;
    if (i < BN) {
        g_cnt[i] = 0;
        float4 v;
        v.x = actions[2*i];
        v.y = actions[2*i + 1];
        v.z = nf[i];
        v.w = 0.f;
        reinterpret_cast<float4*>(g_x0)[i] = v;
    }
    if (i < Bq*EMB) g_pooled[i] = 0.f;
}

// ---------------- build adjacency buckets (2 edges / thread) -----------------
// Pair (j, j+1), j even, never straddles a TWOE boundary (TWOE even).
__global__ void fill_adj(const int* __restrict__ ei) {
    int j = (blockIdx.x * blockDim.x + threadIdx.x) * 2;
    if (j < BE) {
        int2 sv = *reinterpret_cast<const int2*>(&ei[j]);
        int2 dv = *reinterpret_cast<const int2*>(&ei[j + BE]);
        int bs = (j / TWOE) * Nn;
        int bd = ((j + BE) / TWOE) * Nn;
        int d0 = dv.x + bd, d1 = dv.y + bd;
        int p0 = atomicAdd(&g_cnt[d0], 1);
        if (p0 < CAP) g_adj[d0*CAP + p0] = sv.x + bs;
        int p1 = atomicAdd(&g_cnt[d1], 1);
        if (p1 < CAP) g_adj[d1*CAP + p1] = sv.y + bs;
    }
}

// ---------------- conv1 gather: h1[n] = x0[n] + sum x0[adj(n)] ----------------
__global__ void gather1() {
    int tid = blockIdx.x * blockDim.x + threadIdx.x;
    int n = tid >> 2, t = tid & 3;
    if (n >= BN) return;
    int deg = min(g_cnt[n], CAP);
    float4 a = make_float4(0.f, 0.f, 0.f, 0.f);
    const float4* x0 = reinterpret_cast<const float4*>(g_x0);
    for (int i = t; i < deg; i += 4) {
        float4 v = x0[g_adj[n*CAP + i]];
        a.x += v.x; a.y += v.y; a.z += v.z; a.w += v.w;
    }
#pragma unroll
    for (int off = 2; off >= 1; off >>= 1) {
        a.x += __shfl_xor_sync(0xffffffffu, a.x, off);
        a.y += __shfl_xor_sync(0xffffffffu, a.y, off);
        a.z += __shfl_xor_sync(0xffffffffu, a.z, off);
        a.w += __shfl_xor_sync(0xffffffffu, a.w, off);
    }
    if (t == 0) {
        float4 s = x0[n];
        s.x += a.x; s.y += a.y; s.z += a.z; s.w += a.w;
        reinterpret_cast<float4*>(g_h1)[n] = s;
    }
}

// ---------------- conv2 gather: h2[n] = x1[n] + sum x1[adj(n)]  (x1 fp16) -------
// 16 threads per node, 4 halves (8B) per thread; fp32 accumulation.
__global__ void gather2() {
    int tid = blockIdx.x * blockDim.x + threadIdx.x;
    int n = tid >> 4, t = tid & 15;
    if (n >= BN) return;
    int deg = min(g_cnt[n], CAP);
    const uint2* x1v = reinterpret_cast<const uint2*>(g_x1h);   // 4 halves each
    uint2 sv = x1v[n*16 + t];                                   // self term
    float2 f0 = __half22float2(*reinterpret_cast<__half2*>(&sv.x));
    float2 f1 = __half22float2(*reinterpret_cast<__half2*>(&sv.y));
    float4 a = make_float4(f0.x, f0.y, f1.x, f1.y);
    const int* row = &g_adj[n*CAP];
#pragma unroll 4
    for (int i = 0; i < deg; i++) {
        uint2 v = x1v[row[i]*16 + t];
        float2 g0 = __half22float2(*reinterpret_cast<__half2*>(&v.x));
        float2 g1 = __half22float2(*reinterpret_cast<__half2*>(&v.y));
        a.x += g0.x; a.y += g0.y; a.z += g1.x; a.w += g1.y;
    }
    reinterpret_cast<float4*>(g_h2)[n*16 + t] = a;
}

// =====================================================================
// MLP 1 : x1 = relu( relu(h1@W1+b1) @ W2 + b2 ), K=3.   (R9 config)
// 128 nodes/block, 256 threads (16tx x 16ty); 8-row thread tiles.
// =====================================================================
__global__ void __launch_bounds__(256, 2) mlp1_kernel(const float* __restrict__ W1,
                                                      const float* __restrict__ b1,
                                                      const float* __restrict__ W2,
                                                      const float* __restrict__ b2)
{
    extern __shared__ float sm[];
    float* As  = sm;                  // 512
    float* W1s = sm + 512;            // 512 (384 used)
    float* W2s = sm + 1024;           // 8192
    float* Hs  = sm + 9216;           // 128*HSTR = 16896
    float* b1s = sm + 9216 + 128*HSTR;            // 128
    float* b2s = b1s + 128;                       // 64

    int tid = threadIdx.x;
    int tx = tid & 15, ty = tid >> 4;
    int node0 = blockIdx.x * 128;

    for (int e = tid; e < 512; e += 256) As[e] = g_h1[node0*4 + e];
    for (int e = tid; e < 3*HID; e += 256) W1s[e] = W1[e];
    for (int e = tid; e < HID*EMB; e += 256) W2s[e] = W2[e];
    if (tid < HID) b1s[tid] = b1[tid];
    if (tid < EMB) b2s[tid] = b2[tid];
    __syncthreads();

    // ---- layer 1 (K=3): rows ty*8+i, cols tx*8 ----
    ull acc[8][4];
#pragma unroll
    for (int i = 0; i < 8; i++)
#pragma unroll
        for (int j = 0; j < 4; j++)
            acc[i][j] = pack2(b1s[tx*8 + 2*j], b1s[tx*8 + 2*j + 1]);
#pragma unroll
    for (int k = 0; k < 3; k++) {
        float4 w0 = *reinterpret_cast<const float4*>(&W1s[k*HID + tx*8]);
        float4 w1 = *reinterpret_cast<const float4*>(&W1s[k*HID + tx*8 + 4]);
        ull wp[4] = {pack2(w0.x, w0.y), pack2(w0.z, w0.w),
                     pack2(w1.x, w1.y), pack2(w1.z, w1.w)};
#pragma unroll
        for (int i = 0; i < 8; i++) {
            float av = As[(ty*8 + i)*4 + k];
            ull ap = pack2(av, av);
#pragma unroll
            for (int j = 0; j < 4; j++) fma2(acc[i][j], ap, wp[j]);
        }
    }
    // relu -> Hs[128][HSTR]
#pragma unroll
    for (int i = 0; i < 8; i++) {
        float v[8];
#pragma unroll
        for (int j = 0; j < 4; j++) unpack2(acc[i][j], v[2*j], v[2*j+1]);
        float4 r0, r1;
        r0.x = fmaxf(v[0], 0.f); r0.y = fmaxf(v[1], 0.f);
        r0.z = fmaxf(v[2], 0.f); r0.w = fmaxf(v[3], 0.f);
        r1.x = fmaxf(v[4], 0.f); r1.y = fmaxf(v[5], 0.f);
        r1.z = fmaxf(v[6], 0.f); r1.w = fmaxf(v[7], 0.f);
        *reinterpret_cast<float4*>(&Hs[(ty*8 + i)*HSTR + tx*8])     = r0;
        *reinterpret_cast<float4*>(&Hs[(ty*8 + i)*HSTR + tx*8 + 4]) = r1;
    }
    __syncthreads();

    // ---- layer 2: rows ty*8+i (128), cols tx*4 (64) ----
    ull acc2[8][2];
#pragma unroll
    for (int i = 0; i < 8; i++)
#pragma unroll
        for (int j = 0; j < 2; j++)
            acc2[i][j] = pack2(b2s[tx*4 + 2*j], b2s[tx*4 + 2*j + 1]);

    for (int k4 = 0; k4 < 32; k4++) {
        float4 a[8];
#pragma unroll
        for (int i = 0; i < 8; i++)
            a[i] = *reinterpret_cast<const float4*>(&Hs[(ty*8 + i)*HSTR + k4*4]);
#pragma unroll
        for (int s = 0; s < 4; s++) {
            int k = k4*4 + s;
            float4 w = *reinterpret_cast<const float4*>(&W2s[k*EMB + tx*4]);
            ull wp0 = pack2(w.x, w.y), wp1 = pack2(w.z, w.w);
#pragma unroll
            for (int i = 0; i < 8; i++) {
                float av = f4c(a[i], s);
                ull ap = pack2(av, av);
                fma2(acc2[i][0], ap, wp0);
                fma2(acc2[i][1], ap, wp1);
            }
        }
    }
    // relu -> x1 (fp16)
#pragma unroll
    for (int i = 0; i < 8; i++) {
        float v0, v1, v2, v3;
        unpack2(acc2[i][0], v0, v1);
        unpack2(acc2[i][1], v2, v3);
        int node = node0 + ty*8 + i;
        __half2* p = reinterpret_cast<__half2*>(&g_x1h[node*EMB + tx*4]);
        p[0] = __float22half2_rn(make_float2(fmaxf(v0, 0.f), fmaxf(v1, 0.f)));
        p[1] = __float22half2_rn(make_float2(fmaxf(v2, 0.f), fmaxf(v3, 0.f)));
    }
}

// =====================================================================
// MLP 2 + pool.   (R9 config)
// 128 nodes/block, 256 threads. Phase-union smem:
// [0,16896): phase1 = As(8192)+W1(8192); phase2 = Hs(128*HSTR).
// =====================================================================
__global__ void __launch_bounds__(256, 2) mlp2_kernel(const float* __restrict__ W1,
                                                      const float* __restrict__ b1,
                                                      const float* __restrict__ W2,
                                                      const float* __restrict__ b2)
{
    extern __shared__ float sm[];
    float* As  = sm;                  // phase1: 8192
    float* W1s = sm + 8192;           // phase1: 8192
    float* Hs  = sm;                  // phase2: 128*HSTR = 16896 (overlay)
    float* W2s = sm + 16896;          // 8192
    float* b1s = sm + 25088;          // 128
    float* b2s = b1s + 128;           // 64
    float* ps  = b2s + 64;            // 128 pool slots (2 batches)

    int tid = threadIdx.x;
    int tx = tid & 15, ty = tid >> 4;
    int node0 = blockIdx.x * 128;
    int b0 = node0 / Nn;

    for (int e = tid; e < 128*64; e += 256) As[e] = g_h2[node0*64 + e];
    for (int e = tid; e < EMB*HID; e += 256) W1s[e] = W1[e];
    for (int e = tid; e < HID*EMB; e += 256) W2s[e] = W2[e];
    if (tid < HID) b1s[tid] = b1[tid];
    if (tid < EMB) b2s[tid] = b2[tid];
    if (tid < 128) ps[tid] = 0.f;
    __syncthreads();

    // ---- layer 1: rows ty*8+i, cols tx*8; K=64; acc in regs ----
    ull acc[8][4];
#pragma unroll
    for (int i = 0; i < 8; i++)
#pragma unroll
        for (int j = 0; j < 4; j++)
            acc[i][j] = pack2(b1s[tx*8 + 2*j], b1s[tx*8 + 2*j + 1]);

    for (int k4 = 0; k4 < 16; k4++) {
        float4 a[8];
#pragma unroll
        for (int i = 0; i < 8; i++)
            a[i] = *reinterpret_cast<const float4*>(&As[(ty*8 + i)*64 + k4*4]);
#pragma unroll
        for (int s = 0; s < 4; s++) {
            int k = k4*4 + s;
            float4 w0 = *reinterpret_cast<const float4*>(&W1s[k*HID + tx*8]);
            float4 w1 = *reinterpret_cast<const float4*>(&W1s[k*HID + tx*8 + 4]);
            ull wp[4] = {pack2(w0.x, w0.y), pack2(w0.z, w0.w),
                         pack2(w1.x, w1.y), pack2(w1.z, w1.w)};
#pragma unroll
            for (int i = 0; i < 8; i++) {
                float av = f4c(a[i], s);
                ull ap = pack2(av, av);
#pragma unroll
                for (int j = 0; j < 4; j++) fma2(acc[i][j], ap, wp[j]);
            }
        }
    }
    __syncthreads();                  // all reads of As + W1 complete

    // relu -> Hs (overlays As/W1 region)
#pragma unroll
    for (int i = 0; i < 8; i++) {
        float v[8];
#pragma unroll
        for (int j = 0; j < 4; j++) unpack2(acc[i][j], v[2*j], v[2*j+1]);
        float4 r0, r1;
        r0.x = fmaxf(v[0], 0.f); r0.y = fmaxf(v[1], 0.f);
        r0.z = fmaxf(v[2], 0.f); r0.w = fmaxf(v[3], 0.f);
        r1.x = fmaxf(v[4], 0.f); r1.y = fmaxf(v[5], 0.f);
        r1.z = fmaxf(v[6], 0.f); r1.w = fmaxf(v[7], 0.f);
        *reinterpret_cast<float4*>(&Hs[(ty*8 + i)*HSTR + tx*8])     = r0;
        *reinterpret_cast<float4*>(&Hs[(ty*8 + i)*HSTR + tx*8 + 4]) = r1;
    }
    __syncthreads();

    // ---- layer 2: rows ty*8+i (128), cols tx*4 (64) ----
    ull acc2[8][2];
#pragma unroll
    for (int i = 0; i < 8; i++)
#pragma unroll
        for (int j = 0; j < 2; j++)
            acc2[i][j] = pack2(b2s[tx*4 + 2*j], b2s[tx*4 + 2*j + 1]);

    for (int k4 = 0; k4 < 32; k4++) {
        float4 a[8];
#pragma unroll
        for (int i = 0; i < 8; i++)
            a[i] = *reinterpret_cast<const float4*>(&Hs[(ty*8 + i)*HSTR + k4*4]);
#pragma unroll
        for (int s = 0; s < 4; s++) {
            int k = k4*4 + s;
            float4 w = *reinterpret_cast<const float4*>(&W2s[k*EMB + tx*4]);
            ull wp0 = pack2(w.x, w.y), wp1 = pack2(w.z, w.w);
#pragma unroll
            for (int i = 0; i < 8; i++) {
                float av = f4c(a[i], s);
                ull ap = pack2(av, av);
                fma2(acc2[i][0], ap, wp0);
                fma2(acc2[i][1], ap, wp1);
            }
        }
    }

    // relu + pool (register pre-reduce over this thread's 8 rows)
    float osum[2][4] = {{0.f,0.f,0.f,0.f},{0.f,0.f,0.f,0.f}};
#pragma unroll
    for (int i = 0; i < 8; i++) {
        float v[4];
        unpack2(acc2[i][0], v[0], v[1]);
        unpack2(acc2[i][1], v[2], v[3]);
        int node = node0 + ty*8 + i;
        int slot = (node / Nn == b0) ? 0 : 1;
#pragma unroll
        for (int j = 0; j < 4; j++) {
            float r = fmaxf(v[j], 0.f);
            if (slot == 0) osum[0][j] += r; else osum[1][j] += r;
        }
    }
#pragma unroll
    for (int s = 0; s < 2; s++)
#pragma unroll
        for (int j = 0; j < 4; j++)
            if (osum[s][j] != 0.f) atomicAdd(&ps[s*64 + tx*4 + j], osum[s][j]);
    __syncthreads();

    if (tid < 128) {
        int slot = tid >> 6, c = tid & 63;
        int b = b0 + slot;
        if (b < Bq && ps[tid] != 0.f) atomicAdd(&g_pooled[b*EMB + c], ps[tid]);
    }
}

// ---------------- hidden = relu(pooled @ mlp_w + mlp_b)  [8 x 128] ----------------
__global__ void head_kernel(const float* __restrict__ mlp_w, const float* __restrict__ mlp_b) {
    int t = threadIdx.x;              // 1024
    int b = t >> 7, l = t & 127;
    float acc = mlp_b[l];
    for (int k = 0; k < EMB; k++)
        acc += g_pooled[b*EMB + k] * mlp_w[k*HID + l];
    g_hidden[t] = fmaxf(acc, 0.f);
}

// ---------------- out = sigmoid(hidden @ out_w + out_b)  [8 x N] ----------------
__global__ void __launch_bounds__(512) out_kernel(const float* __restrict__ out_w,
                                                  const float* __restrict__ out_b,
                                                  float* __restrict__ out) {
    __shared__ float hs[Bq*HID];
    __shared__ float red[Bq*512];
    int tid = threadIdx.x;
    for (int e = tid; e < Bq*HID; e += 512) hs[e] = g_hidden[e];
    __syncthreads();
    int nl = tid & 127, hg = tid >> 7;
    int n = blockIdx.x * 128 + nl;
    float acc[Bq];
#pragma unroll
    for (int b = 0; b < Bq; b++) acc[b] = 0.f;
    if (n < Nn) {
        int h0 = hg * 32;
        for (int h = h0; h < h0 + 32; h++) {
            float w = out_w[h*Nn + n];
#pragma unroll
            for (int b = 0; b < Bq; b++) acc[b] += hs[b*HID + h] * w;
        }
    }
#pragma unroll
    for (int b = 0; b < Bq; b++) red[b*512 + hg*128 + nl] = acc[b];
    __syncthreads();
    if (hg == 0 && n < Nn) {
        float ob = out_b[n];
#pragma unroll
        for (int b = 0; b < Bq; b++) {
            float s = red[b*512 + nl] + red[b*512 + 128 + nl]
                    + red[b*512 + 256 + nl] + red[b*512 + 384 + nl] + ob;
            out[b*Nn + n] = 1.f / (1.f + expf(-s));
        }
    }
}

// ---------------- launch ----------------
extern "C" void kernel_launch(void* const* d_in, const int* in_sizes, int n_in,
                              void* d_out, int out_size) {
    const float* actions = (const float*)d_in[0];
    const float* nf      = (const float*)d_in[1];
    const int*   ei      = (const int*)d_in[2];     // int32 (JAX x64 disabled)
    const float* c1w1 = (const float*)d_in[3];
    const float* c1b1 = (const float*)d_in[4];
    const float* c1w2 = (const float*)d_in[5];
    const float* c1b2 = (const float*)d_in[6];
    const float* c2w1 = (const float*)d_in[7];
    const float* c2b1 = (const float*)d_in[8];
    const float* c2w2 = (const float*)d_in[9];
    const float* c2b2 = (const float*)d_in[10];
    const float* mlpw = (const float*)d_in[11];
    const float* mlpb = (const float*)d_in[12];
    const float* outw = (const float*)d_in[13];
    const float* outb = (const float*)d_in[14];
    float* out = (float*)d_out;

    const int SMEM1 = (9216 + 128*HSTR + 128 + 64) * 4;          // 104,192 B
    const int SMEM2 = (16896 + 8192 + 128 + 64 + 128) * 4;       // 101,632 B
    cudaFuncSetAttribute(mlp1_kernel, cudaFuncAttributeMaxDynamicSharedMemorySize, SMEM1);
    cudaFuncSetAttribute(mlp2_kernel, cudaFuncAttributeMaxDynamicSharedMemorySize, SMEM2);

    init_kernel<<<(BN + 255)/256, 256>>>(actions, nf);
    fill_adj<<<(BE/2 + 255)/256, 256>>>(ei);
    gather1<<<(BN*4 + 255)/256, 256>>>();
    mlp1_kernel<<<BN/128, 256, SMEM1>>>(c1w1, c1b1, c1w2, c1b2);
    gather2<<<(BN*16 + 255)/256, 256>>>();
    mlp2_kernel<<<BN/128, 256, SMEM2>>>(c2w1, c2b1, c2w2, c2b2);
    head_kernel<<<1, 1024>>>(mlpw, mlpb);
    out_kernel<<<(Nn + 127)/128, 512>>>(outw, outb, out);
}